// round 9
// baseline (speedup 1.0000x reference)
#include <cuda_runtime.h>
#include <math.h>
#include <cstdint>

#define NMAX 65536
#define TWO_PI_F  6.283185307179586f
#define PI_F      3.14159265358979f
#define INV_4PI_F 0.07957747154594767f

// ---------------- scratch ----------------
__device__ float d_W1T[2048 * 256];
__device__ float d_W1P[2048 * 256];
__device__ float d_WmidT[3 * 256 * 256];
__device__ float d_WmidR[3 * 256 * 256];
__device__ float d_y[(size_t)NMAX * 2048];
__device__ float d_h[(size_t)4 * NMAX * 256];
__device__ float d_s[(size_t)4 * NMAX * 256];
__device__ float d_g[(size_t)2 * NMAX * 256];
__device__ float d_dfp[(size_t)8 * NMAX * 3];

// ---------------- helpers ----------------
__device__ __forceinline__ uint32_t to_tf32(float f) {
    uint32_t r; asm("cvt.rna.tf32.f32 %0, %1;" : "=r"(r) : "f"(f)); return r;
}
__device__ __forceinline__ float round_tf32(float f) { return __uint_as_float(to_tf32(f)); }
__device__ __forceinline__ void mma_tf32(float* d, const uint32_t* a, const uint32_t* b) {
    asm volatile(
        "mma.sync.aligned.m16n8k8.row.col.f32.tf32.tf32.f32 "
        "{%0,%1,%2,%3}, {%4,%5,%6,%7}, {%8,%9}, {%0,%1,%2,%3};"
        : "+f"(d[0]), "+f"(d[1]), "+f"(d[2]), "+f"(d[3])
        : "r"(a[0]), "r"(a[1]), "r"(a[2]), "r"(a[3]), "r"(b[0]), "r"(b[1]));
}
__device__ __forceinline__ void cp_async16(uint32_t dst, const void* src, bool pred) {
    int sz = pred ? 16 : 0;
    asm volatile("cp.async.cg.shared.global [%0], [%1], 16, %2;"
                 :: "r"(dst), "l"(src), "r"(sz));
}
__device__ __forceinline__ void cp_commit() {
    asm volatile("cp.async.commit_group;" ::: "memory");
}
__device__ __forceinline__ float clip1(float v) { return fminf(fmaxf(v, -1.0f), 1.0f); }

__device__ __forceinline__ void sincos2pi_poly(float r, float* s, float* c) {
    float x = PI_F * r;
    float t = x * x;
    float sp = -1.0f / 5040.0f + t * (1.0f / 362880.0f);
    sp = 1.0f / 120.0f + t * sp;
    sp = -1.0f / 6.0f + t * sp;
    sp = x + x * t * sp;
    float cp = 1.0f / 40320.0f;
    cp = -1.0f / 720.0f + t * cp;
    cp = 1.0f / 24.0f + t * cp;
    cp = -0.5f + t * cp;
    cp = 1.0f + t * cp;
    float u = sp * cp;
    *s = u + u;
    *c = fmaf(-2.0f * sp, sp, 1.0f);
}

// ---------------- merged weight prep ----------------
__global__ void k_prep(const float* __restrict__ W1,
                       const float* __restrict__ W2, const float* __restrict__ W3,
                       const float* __restrict__ W4,
                       float* __restrict__ W1T, float* __restrict__ W1P,
                       float* __restrict__ outT, float* __restrict__ outR) {
    int idx = blockIdx.x * blockDim.x + threadIdx.x;
    if (idx < 524288) {
        int r = idx >> 8, c = idx & 255;
        W1T[(size_t)c * 2048 + r] = round_tf32(W1[idx]);
    } else if (idx < 1048576) {
        int e = idx - 524288;
        int rp = e >> 8, q = e & 255;
        int t = rp >> 8, s = rp & 255;
        int j = (s < 128) ? (t * 128 + s) : (1024 + t * 128 + (s - 128));
        W1P[e] = round_tf32(W1[(size_t)j * 256 + q]);
    } else if (idx < 1245184) {
        int e2 = idx - 1048576;
        int m = e2 >> 16, e = e2 & 65535;
        const float* W = (m == 0) ? W2 : (m == 1) ? W3 : W4;
        float v = round_tf32(W[e]);
        outR[e2] = v;
        int r = e >> 8, c = e & 255;
        outT[(m << 16) + c * 256 + r] = v;
    }
}

// ---------------- RFF features ----------------
__global__ void k_y(const float* __restrict__ x, const float* __restrict__ B,
                    float* __restrict__ y, int n) {
    int idx = blockIdx.x * blockDim.x + threadIdx.x;
    if (idx >= n * 256) return;
    int p = idx >> 8, j0 = (idx & 255) << 2;
    float x0 = clip1(x[p * 3 + 0]);
    float x1 = clip1(x[p * 3 + 1]);
    float x2 = clip1(x[p * 3 + 2]);
    float4 B0 = *(const float4*)(B + j0);
    float4 B1 = *(const float4*)(B + 1024 + j0);
    float4 B2 = *(const float4*)(B + 2048 + j0);
    float tv[4], sv[4], cv[4];
    tv[0] = x0 * B0.x + x1 * B1.x + x2 * B2.x;
    tv[1] = x0 * B0.y + x1 * B1.y + x2 * B2.y;
    tv[2] = x0 * B0.z + x1 * B1.z + x2 * B2.z;
    tv[3] = x0 * B0.w + x1 * B1.w + x2 * B2.w;
    bool mufu = (((idx >> 5) % 3) == 0);
#pragma unroll
    for (int q = 0; q < 4; q++) {
        float r = tv[q] - rintf(tv[q]);
        if (mufu) __sincosf(TWO_PI_F * r, &sv[q], &cv[q]);
        else sincos2pi_poly(r, &sv[q], &cv[q]);
        sv[q] = round_tf32(sv[q]);
        cv[q] = round_tf32(cv[q]);
    }
    *(float4*)(y + (size_t)p * 2048 + j0) = make_float4(sv[0], sv[1], sv[2], sv[3]);
    *(float4*)(y + (size_t)p * 2048 + 1024 + j0) = make_float4(cv[0], cv[1], cv[2], cv[3]);
}

// ---------------- tf32 mma.sync GEMM: 512 threads, 16 warps, warp tile 32x64 ----------------
#define LDSW 36
#define AS (128 * LDSW)
#define BS (256 * LDSW)
#define STG (AS + BS)
#define YSW 260    // y-stage smem row stride (floats); 260*4 % 16 == 0

__device__ __forceinline__ void issue_stage(uint32_t sAb, uint32_t sBb,
        const float* __restrict__ A, int lda,
        const float* __restrict__ Bm, int ldb,
        int p0, int c0, int koff, int tid, int n) {
    const float* Ab = A + (size_t)p0 * lda + koff;
#pragma unroll
    for (int it = 0; it < 2; it++) {
        int lin = tid + 512 * it;
        int row = lin >> 3, q = (lin & 7) << 2;
        cp_async16(sAb + (uint32_t)(row * LDSW + q) * 4, Ab + (size_t)row * lda + q, p0 + row < n);
    }
    const float* Bb = Bm + (size_t)c0 * ldb + koff;
#pragma unroll
    for (int it = 0; it < 4; it++) {
        int lin = tid + 512 * it;
        int row = lin >> 3, q = (lin & 7) << 2;
        cp_async16(sBb + (uint32_t)(row * LDSW + q) * 4, Bb + (size_t)row * ldb + q, true);
    }
}

// EPI 1: softplus->C (round iff rndOut), sigmoid->Cs
// EPI 2: round(v*Sm)->C
// EPI 3: fused df contraction (y staged via smem) -> dfpart
template <int EPI>
__global__ __launch_bounds__(512, 1)
void k_mma(const float* __restrict__ A, int lda,
           const float* __restrict__ Bm, int ldb,
           const float* __restrict__ bias, const float* __restrict__ Sm,
           float* __restrict__ C, float* __restrict__ Cs,
           int ldc, int K, int n, int rndOut,
           const float* __restrict__ Ybuf, const float* __restrict__ Brff,
           float* __restrict__ dfpart) {
    extern __shared__ uint32_t smem[];
    const int tid = threadIdx.x;
    const int p0 = blockIdx.x * 128;
    const int c0 = blockIdx.y * 256;
    const int wid = tid >> 5, lane = tid & 31;
    const int wm = (wid & 3) * 32;
    const int wn = (wid >> 2) * 64;
    const int tr = lane >> 2, tc = lane & 3;

    uint32_t smem_u32 = (uint32_t)__cvta_generic_to_shared(smem);

    float acc[2][8][4];
#pragma unroll
    for (int mi = 0; mi < 2; mi++)
#pragma unroll
        for (int ni = 0; ni < 8; ni++)
#pragma unroll
            for (int q = 0; q < 4; q++) acc[mi][ni][q] = 0.0f;

    const int nst = K >> 5;
    issue_stage(smem_u32, smem_u32 + AS * 4, A, lda, Bm, ldb, p0, c0, 0, tid, n);
    cp_commit();
    issue_stage(smem_u32 + STG * 4, smem_u32 + (STG + AS) * 4, A, lda, Bm, ldb, p0, c0, 32, tid, n);
    cp_commit();

    for (int i = 0; i < nst; i++) {
        if (i + 1 < nst) asm volatile("cp.async.wait_group 1;" ::: "memory");
        else             asm volatile("cp.async.wait_group 0;" ::: "memory");
        __syncthreads();
        if (i + 2 < nst) {
            int sl = (i + 2) % 3;
            issue_stage(smem_u32 + (uint32_t)(sl * STG) * 4,
                        smem_u32 + (uint32_t)(sl * STG + AS) * 4,
                        A, lda, Bm, ldb, p0, c0, (i + 2) * 32, tid, n);
            cp_commit();
        }
        const uint32_t* cA = smem + (i % 3) * STG;
        const uint32_t* cB = cA + AS;
#pragma unroll
        for (int k8 = 0; k8 < 4; k8++) {
            const int kc = k8 * 8 + 2 * tc;
            uint32_t af[2][4], bf[8][2];
#pragma unroll
            for (int mi = 0; mi < 2; mi++) {
                const uint32_t* base = cA + (wm + mi * 16 + tr) * LDSW + kc;
                uint2 lo = *(const uint2*)base;
                uint2 hi = *(const uint2*)(base + 8 * LDSW);
                af[mi][0] = lo.x; af[mi][1] = hi.x; af[mi][2] = lo.y; af[mi][3] = hi.y;
            }
#pragma unroll
            for (int ni = 0; ni < 8; ni++) {
                uint2 b2 = *(const uint2*)(cB + (wn + ni * 8 + tr) * LDSW + kc);
                bf[ni][0] = b2.x; bf[ni][1] = b2.y;
            }
#pragma unroll
            for (int mi = 0; mi < 2; mi++)
#pragma unroll
                for (int ni = 0; ni < 8; ni++)
                    mma_tf32(acc[mi][ni], af[mi], bf[ni]);
        }
        __syncthreads();
    }

    if (EPI == 3) {
        const int jt = c0 >> 1;
        const bool coshalf = (wn >= 128);
        // ---- stage y tile into smem (coalesced): ys[row][0..127]=sin seg, [128..255]=cos seg
        float* ys = (float*)smem;
#pragma unroll
        for (int it = 0; it < 16; it++) {
            int lin = tid + 512 * it;            // 8192 float4
            int row = lin >> 6;                  // 64 float4 per row
            int q = lin & 63;
            int seg = q >> 5, qq = q & 31;
            float4 v = make_float4(0.f, 0.f, 0.f, 0.f);
            if (p0 + row < n)
                v = *(const float4*)(Ybuf + (size_t)(p0 + row) * 2048 +
                                     (seg ? 1024 + jt : jt) + qq * 4);
            *(float4*)(ys + row * YSW + seg * 128 + qq * 4) = v;
        }
        __syncthreads();

        float sum3[2][2][3];
#pragma unroll
        for (int mi = 0; mi < 2; mi++)
#pragma unroll
            for (int hf = 0; hf < 2; hf++)
#pragma unroll
                for (int d = 0; d < 3; d++) sum3[mi][hf][d] = 0.f;

#pragma unroll
        for (int ni = 0; ni < 8; ni++) {
            int cl = wn + ni * 8 + 2 * tc;
            int j = jt + (coshalf ? cl - 128 : cl);
            float2 B0 = *(const float2*)(Brff + j);
            float2 B1 = *(const float2*)(Brff + 1024 + j);
            float2 B2 = *(const float2*)(Brff + 2048 + j);
            // sin-half reads cos values (seg 1 -> smem offset 128 + cl);
            // cos-half reads sin values (seg 0 -> smem offset cl - 128)
            int soff = coshalf ? (cl - 128) : (128 + cl);
#pragma unroll
            for (int mi = 0; mi < 2; mi++) {
#pragma unroll
                for (int hf = 0; hf < 2; hf++) {
                    int p_local = wm + mi * 16 + tr + 8 * hf;
                    float2 t2 = *(const float2*)(ys + p_local * YSW + soff);
                    float f0 = coshalf ? -t2.x : t2.x;
                    float f1 = coshalf ? -t2.y : t2.y;
                    float e0 = acc[mi][ni][2 * hf] * f0;
                    float e1 = acc[mi][ni][2 * hf + 1] * f1;
                    sum3[mi][hf][0] += e0 * B0.x + e1 * B0.y;
                    sum3[mi][hf][1] += e0 * B1.x + e1 * B1.y;
                    sum3[mi][hf][2] += e0 * B2.x + e1 * B2.y;
                }
            }
        }
        float* red = (float*)smem;
        __syncthreads();
#pragma unroll
        for (int mi = 0; mi < 2; mi++)
#pragma unroll
            for (int hf = 0; hf < 2; hf++)
#pragma unroll
                for (int d = 0; d < 3; d++) {
                    float v = sum3[mi][hf][d];
                    v += __shfl_xor_sync(0xffffffffu, v, 1);
                    v += __shfl_xor_sync(0xffffffffu, v, 2);
                    if (tc == 0) {
                        int p_local = wm + mi * 16 + tr + 8 * hf;
                        red[p_local * 16 + d * 4 + (wn >> 6)] = v;
                    }
                }
        __syncthreads();
        if (tid < 128) {
            int p = p0 + tid;
#pragma unroll
            for (int d = 0; d < 3; d++) {
                float s = red[tid * 16 + d * 4 + 0] + red[tid * 16 + d * 4 + 1] +
                          red[tid * 16 + d * 4 + 2] + red[tid * 16 + d * 4 + 3];
                dfpart[((size_t)blockIdx.y * NMAX + p) * 3 + d] = TWO_PI_F * s;
            }
        }
        return;
    }

#pragma unroll
    for (int mi = 0; mi < 2; mi++) {
        const int r0 = p0 + wm + mi * 16 + tr;
#pragma unroll
        for (int ni = 0; ni < 8; ni++) {
            const int gc = c0 + wn + ni * 8 + 2 * tc;
            float2 bia = make_float2(0.f, 0.f);
            if (EPI == 1) bia = *(const float2*)(bias + gc);
#pragma unroll
            for (int hf = 0; hf < 2; hf++) {
                const int p = r0 + 8 * hf;
                if (p >= n) continue;
                float v0 = acc[mi][ni][2 * hf];
                float v1 = acc[mi][ni][2 * hf + 1];
                const size_t off = (size_t)p * ldc + gc;
                if (EPI == 1) {
                    float z0 = v0 + bia.x, z1 = v1 + bia.y;
                    float e0 = __expf(-fabsf(z0)), e1 = __expf(-fabsf(z1));
                    float h0 = fmaxf(z0, 0.f) + log1pf(e0);
                    float h1 = fmaxf(z1, 0.f) + log1pf(e1);
                    float s0 = (z0 >= 0.f) ? 1.f / (1.f + e0) : e0 / (1.f + e0);
                    float s1 = (z1 >= 0.f) ? 1.f / (1.f + e1) : e1 / (1.f + e1);
                    if (rndOut) { h0 = round_tf32(h0); h1 = round_tf32(h1); }
                    *(float2*)(C + off) = make_float2(h0, h1);
                    *(float2*)(Cs + off) = make_float2(s0, s1);
                } else {
                    float2 sm2 = *(const float2*)(Sm + off);
                    *(float2*)(C + off) =
                        make_float2(round_tf32(v0 * sm2.x), round_tf32(v1 * sm2.y));
                }
            }
        }
    }
}

// ---------------- head: f = h4 . W5 + b5, g4 = round(W5 * s4) ----------------
__global__ void k_head(const float* __restrict__ h4, const float* __restrict__ s4,
                       const float* __restrict__ W5, const float* __restrict__ b5,
                       float* __restrict__ out_f, float* __restrict__ g4, int n) {
    __shared__ float sw[256];
    int tid = threadIdx.x;
    sw[tid] = W5[tid];
    __syncthreads();
    int p = blockIdx.x * 8 + (tid >> 5);
    int lane = tid & 31;
    if (p >= n) return;
    float acc = 0.f;
    const float* hr = h4 + (size_t)p * 256;
    const float* sr = s4 + (size_t)p * 256;
    float* gr = g4 + (size_t)p * 256;
#pragma unroll
    for (int i = lane; i < 256; i += 32) {
        float wv = sw[i];
        acc += hr[i] * wv;
        gr[i] = round_tf32(wv * sr[i]);
    }
#pragma unroll
    for (int o = 16; o; o >>= 1) acc += __shfl_xor_sync(0xffffffffu, acc, o);
    if (lane == 0) out_f[p] = acc + b5[0];
}

// ---------------- Biot-Savart ----------------
__global__ void k_biot(const float* __restrict__ x, const float* __restrict__ bdry,
                       float* __restrict__ out_alpha, int n, int M) {
    __shared__ float bx[512], by[512], bz[512];
    __shared__ float sgx[512], sgy[512], sgz[512];
    __shared__ float smx[512], smy[512], smz[512];
    int tid = threadIdx.x;
    for (int m = tid; m < M; m += blockDim.x) {
        bx[m] = bdry[m * 3 + 0];
        by[m] = bdry[m * 3 + 1];
        bz[m] = bdry[m * 3 + 2];
    }
    __syncthreads();
    for (int m = tid; m < M; m += blockDim.x) {
        int m2 = (m + 1) == M ? 0 : m + 1;
        sgx[m] = bx[m2] - bx[m];
        sgy[m] = by[m2] - by[m];
        sgz[m] = bz[m2] - bz[m];
        smx[m] = 0.5f * (bx[m2] + bx[m]);
        smy[m] = 0.5f * (by[m2] + by[m]);
        smz[m] = 0.5f * (bz[m2] + bz[m]);
    }
    __syncthreads();
    int p = blockIdx.x * blockDim.x + tid;
    if (p >= n) return;
    float x0 = clip1(x[p * 3 + 0]);
    float x1 = clip1(x[p * 3 + 1]);
    float x2 = clip1(x[p * 3 + 2]);
    float ax = 0.f, ay = 0.f, az = 0.f;
    for (int m = 0; m < M; m++) {
        float dx = x0 - smx[m], dy = x1 - smy[m], dz = x2 - smz[m];
        float cxv = sgy[m] * dz - sgz[m] * dy;
        float cyv = sgz[m] * dx - sgx[m] * dz;
        float czv = sgx[m] * dy - sgy[m] * dx;
        float r2 = dx * dx + dy * dy + dz * dz;
        float inv = rsqrtf(r2);
        float w = inv * inv * inv;
        ax += cxv * w; ay += cyv * w; az += czv * w;
    }
    out_alpha[p * 3 + 0] = INV_4PI_F * ax;
    out_alpha[p * 3 + 1] = INV_4PI_F * ay;
    out_alpha[p * 3 + 2] = INV_4PI_F * az;
}

// ---------------- finish ----------------
__global__ void k_finish(const float* __restrict__ part, const float* __restrict__ alpha,
                         float* __restrict__ out_df, float* __restrict__ out_cur, int n) {
    int p = blockIdx.x * blockDim.x + threadIdx.x;
    if (p >= n) return;
#pragma unroll
    for (int d = 0; d < 3; d++) {
        float s = 0.f;
#pragma unroll
        for (int t = 0; t < 8; t++) s += part[((size_t)t * NMAX + p) * 3 + d];
        out_df[p * 3 + d] = s;
        out_cur[p * 3 + d] = s + alpha[p * 3 + d];
    }
}

// ---------------- launcher ----------------
extern "C" void kernel_launch(void* const* d_in, const int* in_sizes, int n_in,
                              void* d_out, int out_size) {
    const float* x    = (const float*)d_in[0];
    const float* bdry = (const float*)d_in[1];
    const float* B    = (const float*)d_in[2];
    const float* W1   = (const float*)d_in[3];
    const float* b1   = (const float*)d_in[4];
    const float* W2   = (const float*)d_in[5];
    const float* b2   = (const float*)d_in[6];
    const float* W3   = (const float*)d_in[7];
    const float* b3   = (const float*)d_in[8];
    const float* W4   = (const float*)d_in[9];
    const float* b4   = (const float*)d_in[10];
    const float* W5   = (const float*)d_in[11];
    const float* b5   = (const float*)d_in[12];

    int n = in_sizes[0] / 3;
    int M = in_sizes[1] / 3;

    float* out = (float*)d_out;
    float* out_f     = out;
    float* out_cur   = out + (size_t)n;
    float* out_df    = out + (size_t)4 * n;
    float* out_alpha = out + (size_t)7 * n;

    void* pv;
    cudaGetSymbolAddress(&pv, d_W1T);   float* W1T = (float*)pv;
    cudaGetSymbolAddress(&pv, d_W1P);   float* W1P = (float*)pv;
    cudaGetSymbolAddress(&pv, d_WmidT); float* WmT = (float*)pv;
    cudaGetSymbolAddress(&pv, d_WmidR); float* WmR = (float*)pv;
    cudaGetSymbolAddress(&pv, d_y);     float* yb  = (float*)pv;
    cudaGetSymbolAddress(&pv, d_h);     float* hb  = (float*)pv;
    cudaGetSymbolAddress(&pv, d_s);     float* sb  = (float*)pv;
    cudaGetSymbolAddress(&pv, d_g);     float* gb  = (float*)pv;
    cudaGetSymbolAddress(&pv, d_dfp);   float* dfp = (float*)pv;

    float *W2T = WmT, *W3T = WmT + 65536, *W4T = WmT + 2 * 65536;
    float *W2R = WmR, *W3R = WmR + 65536, *W4R = WmR + 2 * 65536;

    const size_t HS = (size_t)NMAX * 256;
    float *h1 = hb, *h2 = hb + HS, *h3 = hb + 2 * HS, *h4 = hb + 3 * HS;
    float *s1 = sb, *s2 = sb + HS, *s3 = sb + 2 * HS, *s4 = sb + 3 * HS;
    float *g0 = gb, *g1b = gb + HS;

    const int SMEM = 3 * STG * 4;  // 165888 bytes (>= 128*YSW*4 = 133120 for y staging)
    cudaFuncSetAttribute((const void*)k_mma<1>, cudaFuncAttributeMaxDynamicSharedMemorySize, SMEM);
    cudaFuncSetAttribute((const void*)k_mma<2>, cudaFuncAttributeMaxDynamicSharedMemorySize, SMEM);
    cudaFuncSetAttribute((const void*)k_mma<3>, cudaFuncAttributeMaxDynamicSharedMemorySize, SMEM);

    // weight prep (merged)
    k_prep<<<(1245184 + 255) / 256, 256>>>(W1, W2, W3, W4, W1T, W1P, WmT, WmR);

    // RFF features
    k_y<<<(n * 256 + 255) / 256, 256>>>(x, B, yb, n);

    dim3 g256((n + 127) / 128, 1);
    // forward (layer 4 stores h4 UNROUNDED: feeds f directly)
    k_mma<1><<<g256, 512, SMEM>>>(yb, 2048, W1T, 2048, b1, nullptr, h1, s1, 256, 2048, n, 1,
                                  nullptr, nullptr, nullptr);
    k_mma<1><<<g256, 512, SMEM>>>(h1, 256, W2T, 256, b2, nullptr, h2, s2, 256, 256, n, 1,
                                  nullptr, nullptr, nullptr);
    k_mma<1><<<g256, 512, SMEM>>>(h2, 256, W3T, 256, b3, nullptr, h3, s3, 256, 256, n, 1,
                                  nullptr, nullptr, nullptr);
    k_mma<1><<<g256, 512, SMEM>>>(h3, 256, W4T, 256, b4, nullptr, h4, s4, 256, 256, n, 0,
                                  nullptr, nullptr, nullptr);

    // head
    k_head<<<(n + 7) / 8, 256>>>(h4, s4, W5, b5, out_f, g0, n);

    // backward
    k_mma<2><<<g256, 512, SMEM>>>(g0, 256, W4R, 256, nullptr, s3, g1b, nullptr, 256, 256, n, 1,
                                  nullptr, nullptr, nullptr);
    k_mma<2><<<g256, 512, SMEM>>>(g1b, 256, W3R, 256, nullptr, s2, g0, nullptr, 256, 256, n, 1,
                                  nullptr, nullptr, nullptr);
    k_mma<2><<<g256, 512, SMEM>>>(g0, 256, W2R, 256, nullptr, s1, g1b, nullptr, 256, 256, n, 1,
                                  nullptr, nullptr, nullptr);

    // alpha
    k_biot<<<(n + 255) / 256, 256>>>(x, bdry, out_alpha, n, M);

    // gy GEMM fused with df contraction (y staged through smem)
    dim3 gGy((n + 127) / 128, 8);
    k_mma<3><<<gGy, 512, SMEM>>>(g1b, 256, W1P, 256, nullptr, nullptr, nullptr, nullptr, 256, 256, n, 0,
                                 yb, B, dfp);

    // finish
    k_finish<<<(n + 255) / 256, 256>>>(dfp, out_alpha, out_df, out_cur, n);
}

// round 10
// speedup vs baseline: 1.0010x; 1.0010x over previous
#include <cuda_runtime.h>
#include <math.h>
#include <cstdint>

#define NMAX 65536
#define TWO_PI_F  6.283185307179586f
#define PI_F      3.14159265358979f
#define INV_4PI_F 0.07957747154594767f

// ---------------- scratch ----------------
__device__ float d_W1T[2048 * 256];
__device__ float d_W1P[2048 * 256];
__device__ float d_WmidT[3 * 256 * 256];
__device__ float d_WmidR[3 * 256 * 256];
__device__ float d_y[(size_t)NMAX * 2048];
__device__ float d_h[(size_t)4 * NMAX * 256];
__device__ float d_s[(size_t)4 * NMAX * 256];
__device__ float d_g[(size_t)2 * NMAX * 256];
__device__ float d_dfp[(size_t)8 * NMAX * 3];

// ---------------- helpers ----------------
__device__ __forceinline__ uint32_t to_tf32(float f) {
    uint32_t r; asm("cvt.rna.tf32.f32 %0, %1;" : "=r"(r) : "f"(f)); return r;
}
__device__ __forceinline__ float round_tf32(float f) { return __uint_as_float(to_tf32(f)); }
__device__ __forceinline__ void mma_tf32(float* d, const uint32_t* a, const uint32_t* b) {
    asm volatile(
        "mma.sync.aligned.m16n8k8.row.col.f32.tf32.tf32.f32 "
        "{%0,%1,%2,%3}, {%4,%5,%6,%7}, {%8,%9}, {%0,%1,%2,%3};"
        : "+f"(d[0]), "+f"(d[1]), "+f"(d[2]), "+f"(d[3])
        : "r"(a[0]), "r"(a[1]), "r"(a[2]), "r"(a[3]), "r"(b[0]), "r"(b[1]));
}
__device__ __forceinline__ void cp_async16(uint32_t dst, const void* src, bool pred) {
    int sz = pred ? 16 : 0;
    asm volatile("cp.async.cg.shared.global [%0], [%1], 16, %2;"
                 :: "r"(dst), "l"(src), "r"(sz));
}
__device__ __forceinline__ void cp_commit() {
    asm volatile("cp.async.commit_group;" ::: "memory");
}
__device__ __forceinline__ float clip1(float v) { return fminf(fmaxf(v, -1.0f), 1.0f); }

__device__ __forceinline__ void sincos2pi_poly(float r, float* s, float* c) {
    float x = PI_F * r;
    float t = x * x;
    float sp = -1.0f / 5040.0f + t * (1.0f / 362880.0f);
    sp = 1.0f / 120.0f + t * sp;
    sp = -1.0f / 6.0f + t * sp;
    sp = x + x * t * sp;
    float cp = 1.0f / 40320.0f;
    cp = -1.0f / 720.0f + t * cp;
    cp = 1.0f / 24.0f + t * cp;
    cp = -0.5f + t * cp;
    cp = 1.0f + t * cp;
    float u = sp * cp;
    *s = u + u;
    *c = fmaf(-2.0f * sp, sp, 1.0f);
}

// ---------------- weight prep (R5 structure) ----------------
__global__ void k_tr(const float* __restrict__ in, float* __restrict__ out, int R, int C) {
    int idx = blockIdx.x * blockDim.x + threadIdx.x;
    if (idx >= R * C) return;
    int r = idx / C, c = idx - r * C;
    out[(size_t)c * R + r] = round_tf32(in[idx]);
}
__global__ void k_prep_mid(const float* __restrict__ W2, const float* __restrict__ W3,
                           const float* __restrict__ W4,
                           float* __restrict__ outT, float* __restrict__ outR) {
    int idx = blockIdx.x * blockDim.x + threadIdx.x;
    if (idx >= 3 * 65536) return;
    int m = idx >> 16, e = idx & 65535;
    const float* W = (m == 0) ? W2 : (m == 1) ? W3 : W4;
    float v = round_tf32(W[e]);
    outR[idx] = v;
    int r = e >> 8, c = e & 255;
    outT[(m << 16) + c * 256 + r] = v;
}
__global__ void k_perm(const float* __restrict__ W1, float* __restrict__ out) {
    int idx = blockIdx.x * blockDim.x + threadIdx.x;
    if (idx >= 2048 * 256) return;
    int rp = idx >> 8, q = idx & 255;
    int t = rp >> 8, s = rp & 255;
    int j = (s < 128) ? (t * 128 + s) : (1024 + t * 128 + (s - 128));
    out[idx] = round_tf32(W1[(size_t)j * 256 + q]);
}

// ---------------- RFF features ----------------
__global__ void k_y(const float* __restrict__ x, const float* __restrict__ B,
                    float* __restrict__ y, int n) {
    int idx = blockIdx.x * blockDim.x + threadIdx.x;
    if (idx >= n * 256) return;
    int p = idx >> 8, j0 = (idx & 255) << 2;
    float x0 = clip1(x[p * 3 + 0]);
    float x1 = clip1(x[p * 3 + 1]);
    float x2 = clip1(x[p * 3 + 2]);
    float4 B0 = *(const float4*)(B + j0);
    float4 B1 = *(const float4*)(B + 1024 + j0);
    float4 B2 = *(const float4*)(B + 2048 + j0);
    float tv[4], sv[4], cv[4];
    tv[0] = x0 * B0.x + x1 * B1.x + x2 * B2.x;
    tv[1] = x0 * B0.y + x1 * B1.y + x2 * B2.y;
    tv[2] = x0 * B0.z + x1 * B1.z + x2 * B2.z;
    tv[3] = x0 * B0.w + x1 * B1.w + x2 * B2.w;
    bool mufu = (((idx >> 5) % 3) == 0);
#pragma unroll
    for (int q = 0; q < 4; q++) {
        float r = tv[q] - rintf(tv[q]);
        if (mufu) __sincosf(TWO_PI_F * r, &sv[q], &cv[q]);
        else sincos2pi_poly(r, &sv[q], &cv[q]);
        sv[q] = round_tf32(sv[q]);
        cv[q] = round_tf32(cv[q]);
    }
    *(float4*)(y + (size_t)p * 2048 + j0) = make_float4(sv[0], sv[1], sv[2], sv[3]);
    *(float4*)(y + (size_t)p * 2048 + 1024 + j0) = make_float4(cv[0], cv[1], cv[2], cv[3]);
}

// ---------------- tf32 mma.sync GEMM: 512 threads, 16 warps, warp tile 32x64 ----------------
#define LDSW 36
#define AS (128 * LDSW)
#define BS (256 * LDSW)
#define STG (AS + BS)

__device__ __forceinline__ void issue_stage(uint32_t sAb, uint32_t sBb,
        const float* __restrict__ A, int lda,
        const float* __restrict__ Bm, int ldb,
        int p0, int c0, int koff, int tid, int n) {
    const float* Ab = A + (size_t)p0 * lda + koff;
#pragma unroll
    for (int it = 0; it < 2; it++) {
        int lin = tid + 512 * it;
        int row = lin >> 3, q = (lin & 7) << 2;
        cp_async16(sAb + (uint32_t)(row * LDSW + q) * 4, Ab + (size_t)row * lda + q, p0 + row < n);
    }
    const float* Bb = Bm + (size_t)c0 * ldb + koff;
#pragma unroll
    for (int it = 0; it < 4; it++) {
        int lin = tid + 512 * it;
        int row = lin >> 3, q = (lin & 7) << 2;
        cp_async16(sBb + (uint32_t)(row * LDSW + q) * 4, Bb + (size_t)row * ldb + q, true);
    }
}

// EPI 1: softplus->C (round iff rndOut), sigmoid->Cs
// EPI 2: round(v*Sm)->C
// EPI 3: fused df contraction -> dfpart
template <int EPI>
__global__ __launch_bounds__(512, 1)
void k_mma(const float* __restrict__ A, int lda,
           const float* __restrict__ Bm, int ldb,
           const float* __restrict__ bias, const float* __restrict__ Sm,
           float* __restrict__ C, float* __restrict__ Cs,
           int ldc, int K, int n, int rndOut,
           const float* __restrict__ Ybuf, const float* __restrict__ Brff,
           float* __restrict__ dfpart) {
    extern __shared__ uint32_t smem[];
    const int tid = threadIdx.x;
    const int p0 = blockIdx.x * 128;
    const int c0 = blockIdx.y * 256;
    const int wid = tid >> 5, lane = tid & 31;
    const int wm = (wid & 3) * 32;
    const int wn = (wid >> 2) * 64;
    const int tr = lane >> 2, tc = lane & 3;

    uint32_t smem_u32 = (uint32_t)__cvta_generic_to_shared(smem);

    float acc[2][8][4];
#pragma unroll
    for (int mi = 0; mi < 2; mi++)
#pragma unroll
        for (int ni = 0; ni < 8; ni++)
#pragma unroll
            for (int q = 0; q < 4; q++) acc[mi][ni][q] = 0.0f;

    const int nst = K >> 5;
    issue_stage(smem_u32, smem_u32 + AS * 4, A, lda, Bm, ldb, p0, c0, 0, tid, n);
    cp_commit();
    issue_stage(smem_u32 + STG * 4, smem_u32 + (STG + AS) * 4, A, lda, Bm, ldb, p0, c0, 32, tid, n);
    cp_commit();

    for (int i = 0; i < nst; i++) {
        if (i + 1 < nst) asm volatile("cp.async.wait_group 1;" ::: "memory");
        else             asm volatile("cp.async.wait_group 0;" ::: "memory");
        __syncthreads();
        if (i + 2 < nst) {
            int sl = (i + 2) % 3;
            issue_stage(smem_u32 + (uint32_t)(sl * STG) * 4,
                        smem_u32 + (uint32_t)(sl * STG + AS) * 4,
                        A, lda, Bm, ldb, p0, c0, (i + 2) * 32, tid, n);
            cp_commit();
        }
        const uint32_t* cA = smem + (i % 3) * STG;
        const uint32_t* cB = cA + AS;
#pragma unroll
        for (int k8 = 0; k8 < 4; k8++) {
            const int kc = k8 * 8 + 2 * tc;
            uint32_t af[2][4], bf[8][2];
#pragma unroll
            for (int mi = 0; mi < 2; mi++) {
                const uint32_t* base = cA + (wm + mi * 16 + tr) * LDSW + kc;
                uint2 lo = *(const uint2*)base;
                uint2 hi = *(const uint2*)(base + 8 * LDSW);
                af[mi][0] = lo.x; af[mi][1] = hi.x; af[mi][2] = lo.y; af[mi][3] = hi.y;
            }
#pragma unroll
            for (int ni = 0; ni < 8; ni++) {
                uint2 b2 = *(const uint2*)(cB + (wn + ni * 8 + tr) * LDSW + kc);
                bf[ni][0] = b2.x; bf[ni][1] = b2.y;
            }
#pragma unroll
            for (int mi = 0; mi < 2; mi++)
#pragma unroll
                for (int ni = 0; ni < 8; ni++)
                    mma_tf32(acc[mi][ni], af[mi], bf[ni]);
        }
        __syncthreads();
    }

    if (EPI == 3) {
        const int jt = c0 >> 1;
        const bool coshalf = (wn >= 128);
        float sum3[2][2][3];
#pragma unroll
        for (int mi = 0; mi < 2; mi++)
#pragma unroll
            for (int hf = 0; hf < 2; hf++)
#pragma unroll
                for (int d = 0; d < 3; d++) sum3[mi][hf][d] = 0.f;

#pragma unroll
        for (int ni = 0; ni < 8; ni++) {
            int cl = wn + ni * 8 + 2 * tc;
            int j = jt + (coshalf ? cl - 128 : cl);
            float2 B0 = *(const float2*)(Brff + j);
            float2 B1 = *(const float2*)(Brff + 1024 + j);
            float2 B2 = *(const float2*)(Brff + 2048 + j);
            int yoff = coshalf ? j : (1024 + j);
#pragma unroll
            for (int mi = 0; mi < 2; mi++) {
#pragma unroll
                for (int hf = 0; hf < 2; hf++) {
                    int p = p0 + wm + mi * 16 + tr + 8 * hf;
                    float2 t2 = *(const float2*)(Ybuf + (size_t)p * 2048 + yoff);
                    float f0 = coshalf ? -t2.x : t2.x;
                    float f1 = coshalf ? -t2.y : t2.y;
                    float e0 = acc[mi][ni][2 * hf] * f0;
                    float e1 = acc[mi][ni][2 * hf + 1] * f1;
                    sum3[mi][hf][0] += e0 * B0.x + e1 * B0.y;
                    sum3[mi][hf][1] += e0 * B1.x + e1 * B1.y;
                    sum3[mi][hf][2] += e0 * B2.x + e1 * B2.y;
                }
            }
        }
        float* red = (float*)smem;
        __syncthreads();
#pragma unroll
        for (int mi = 0; mi < 2; mi++)
#pragma unroll
            for (int hf = 0; hf < 2; hf++)
#pragma unroll
                for (int d = 0; d < 3; d++) {
                    float v = sum3[mi][hf][d];
                    v += __shfl_xor_sync(0xffffffffu, v, 1);
                    v += __shfl_xor_sync(0xffffffffu, v, 2);
                    if (tc == 0) {
                        int p_local = wm + mi * 16 + tr + 8 * hf;
                        red[p_local * 16 + d * 4 + (wn >> 6)] = v;
                    }
                }
        __syncthreads();
        if (tid < 128) {
            int p = p0 + tid;
#pragma unroll
            for (int d = 0; d < 3; d++) {
                float s = red[tid * 16 + d * 4 + 0] + red[tid * 16 + d * 4 + 1] +
                          red[tid * 16 + d * 4 + 2] + red[tid * 16 + d * 4 + 3];
                dfpart[((size_t)blockIdx.y * NMAX + p) * 3 + d] = TWO_PI_F * s;
            }
        }
        return;
    }

#pragma unroll
    for (int mi = 0; mi < 2; mi++) {
        const int r0 = p0 + wm + mi * 16 + tr;
#pragma unroll
        for (int ni = 0; ni < 8; ni++) {
            const int gc = c0 + wn + ni * 8 + 2 * tc;
            float2 bia = make_float2(0.f, 0.f);
            if (EPI == 1) bia = *(const float2*)(bias + gc);
#pragma unroll
            for (int hf = 0; hf < 2; hf++) {
                const int p = r0 + 8 * hf;
                if (p >= n) continue;
                float v0 = acc[mi][ni][2 * hf];
                float v1 = acc[mi][ni][2 * hf + 1];
                const size_t off = (size_t)p * ldc + gc;
                if (EPI == 1) {
                    float z0 = v0 + bia.x, z1 = v1 + bia.y;
                    float e0 = __expf(-fabsf(z0)), e1 = __expf(-fabsf(z1));
                    float h0 = fmaxf(z0, 0.f) + log1pf(e0);
                    float h1 = fmaxf(z1, 0.f) + log1pf(e1);
                    float s0 = (z0 >= 0.f) ? 1.f / (1.f + e0) : e0 / (1.f + e0);
                    float s1 = (z1 >= 0.f) ? 1.f / (1.f + e1) : e1 / (1.f + e1);
                    if (rndOut) { h0 = round_tf32(h0); h1 = round_tf32(h1); }
                    *(float2*)(C + off) = make_float2(h0, h1);
                    *(float2*)(Cs + off) = make_float2(s0, s1);
                } else {
                    float2 sm2 = *(const float2*)(Sm + off);
                    *(float2*)(C + off) =
                        make_float2(round_tf32(v0 * sm2.x), round_tf32(v1 * sm2.y));
                }
            }
        }
    }
}

// ---------------- head: f = h4 . W5 + b5, g4 = round(W5 * s4) ----------------
__global__ void k_head(const float* __restrict__ h4, const float* __restrict__ s4,
                       const float* __restrict__ W5, const float* __restrict__ b5,
                       float* __restrict__ out_f, float* __restrict__ g4, int n) {
    __shared__ float sw[256];
    int tid = threadIdx.x;
    sw[tid] = W5[tid];
    __syncthreads();
    int p = blockIdx.x * 8 + (tid >> 5);
    int lane = tid & 31;
    if (p >= n) return;
    float acc = 0.f;
    const float* hr = h4 + (size_t)p * 256;
    const float* sr = s4 + (size_t)p * 256;
    float* gr = g4 + (size_t)p * 256;
#pragma unroll
    for (int i = lane; i < 256; i += 32) {
        float wv = sw[i];
        acc += hr[i] * wv;
        gr[i] = round_tf32(wv * sr[i]);
    }
#pragma unroll
    for (int o = 16; o; o >>= 1) acc += __shfl_xor_sync(0xffffffffu, acc, o);
    if (lane == 0) out_f[p] = acc + b5[0];
}

// ---------------- Biot-Savart ----------------
__global__ void k_biot(const float* __restrict__ x, const float* __restrict__ bdry,
                       float* __restrict__ out_alpha, int n, int M) {
    __shared__ float bx[512], by[512], bz[512];
    __shared__ float sgx[512], sgy[512], sgz[512];
    __shared__ float smx[512], smy[512], smz[512];
    int tid = threadIdx.x;
    for (int m = tid; m < M; m += blockDim.x) {
        bx[m] = bdry[m * 3 + 0];
        by[m] = bdry[m * 3 + 1];
        bz[m] = bdry[m * 3 + 2];
    }
    __syncthreads();
    for (int m = tid; m < M; m += blockDim.x) {
        int m2 = (m + 1) == M ? 0 : m + 1;
        sgx[m] = bx[m2] - bx[m];
        sgy[m] = by[m2] - by[m];
        sgz[m] = bz[m2] - bz[m];
        smx[m] = 0.5f * (bx[m2] + bx[m]);
        smy[m] = 0.5f * (by[m2] + by[m]);
        smz[m] = 0.5f * (bz[m2] + bz[m]);
    }
    __syncthreads();
    int p = blockIdx.x * blockDim.x + tid;
    if (p >= n) return;
    float x0 = clip1(x[p * 3 + 0]);
    float x1 = clip1(x[p * 3 + 1]);
    float x2 = clip1(x[p * 3 + 2]);
    float ax = 0.f, ay = 0.f, az = 0.f;
    for (int m = 0; m < M; m++) {
        float dx = x0 - smx[m], dy = x1 - smy[m], dz = x2 - smz[m];
        float cxv = sgy[m] * dz - sgz[m] * dy;
        float cyv = sgz[m] * dx - sgx[m] * dz;
        float czv = sgx[m] * dy - sgy[m] * dx;
        float r2 = dx * dx + dy * dy + dz * dz;
        float inv = rsqrtf(r2);
        float w = inv * inv * inv;
        ax += cxv * w; ay += cyv * w; az += czv * w;
    }
    out_alpha[p * 3 + 0] = INV_4PI_F * ax;
    out_alpha[p * 3 + 1] = INV_4PI_F * ay;
    out_alpha[p * 3 + 2] = INV_4PI_F * az;
}

// ---------------- finish ----------------
__global__ void k_finish(const float* __restrict__ part, const float* __restrict__ alpha,
                         float* __restrict__ out_df, float* __restrict__ out_cur, int n) {
    int p = blockIdx.x * blockDim.x + threadIdx.x;
    if (p >= n) return;
#pragma unroll
    for (int d = 0; d < 3; d++) {
        float s = 0.f;
#pragma unroll
        for (int t = 0; t < 8; t++) s += part[((size_t)t * NMAX + p) * 3 + d];
        out_df[p * 3 + d] = s;
        out_cur[p * 3 + d] = s + alpha[p * 3 + d];
    }
}

// ---------------- launcher ----------------
extern "C" void kernel_launch(void* const* d_in, const int* in_sizes, int n_in,
                              void* d_out, int out_size) {
    const float* x    = (const float*)d_in[0];
    const float* bdry = (const float*)d_in[1];
    const float* B    = (const float*)d_in[2];
    const float* W1   = (const float*)d_in[3];
    const float* b1   = (const float*)d_in[4];
    const float* W2   = (const float*)d_in[5];
    const float* b2   = (const float*)d_in[6];
    const float* W3   = (const float*)d_in[7];
    const float* b3   = (const float*)d_in[8];
    const float* W4   = (const float*)d_in[9];
    const float* b4   = (const float*)d_in[10];
    const float* W5   = (const float*)d_in[11];
    const float* b5   = (const float*)d_in[12];

    int n = in_sizes[0] / 3;
    int M = in_sizes[1] / 3;

    float* out = (float*)d_out;
    float* out_f     = out;
    float* out_cur   = out + (size_t)n;
    float* out_df    = out + (size_t)4 * n;
    float* out_alpha = out + (size_t)7 * n;

    void* pv;
    cudaGetSymbolAddress(&pv, d_W1T);   float* W1T = (float*)pv;
    cudaGetSymbolAddress(&pv, d_W1P);   float* W1P = (float*)pv;
    cudaGetSymbolAddress(&pv, d_WmidT); float* WmT = (float*)pv;
    cudaGetSymbolAddress(&pv, d_WmidR); float* WmR = (float*)pv;
    cudaGetSymbolAddress(&pv, d_y);     float* yb  = (float*)pv;
    cudaGetSymbolAddress(&pv, d_h);     float* hb  = (float*)pv;
    cudaGetSymbolAddress(&pv, d_s);     float* sb  = (float*)pv;
    cudaGetSymbolAddress(&pv, d_g);     float* gb  = (float*)pv;
    cudaGetSymbolAddress(&pv, d_dfp);   float* dfp = (float*)pv;

    float *W2T = WmT, *W3T = WmT + 65536, *W4T = WmT + 2 * 65536;
    float *W2R = WmR, *W3R = WmR + 65536, *W4R = WmR + 2 * 65536;

    const size_t HS = (size_t)NMAX * 256;
    float *h1 = hb, *h2 = hb + HS, *h3 = hb + 2 * HS, *h4 = hb + 3 * HS;
    float *s1 = sb, *s2 = sb + HS, *s3 = sb + 2 * HS, *s4 = sb + 3 * HS;
    float *g0 = gb, *g1b = gb + HS;

    const int SMEM = 3 * STG * 4;  // 165888 bytes
    cudaFuncSetAttribute((const void*)k_mma<1>, cudaFuncAttributeMaxDynamicSharedMemorySize, SMEM);
    cudaFuncSetAttribute((const void*)k_mma<2>, cudaFuncAttributeMaxDynamicSharedMemorySize, SMEM);
    cudaFuncSetAttribute((const void*)k_mma<3>, cudaFuncAttributeMaxDynamicSharedMemorySize, SMEM);

    // weight prep (R5 structure: separate kernels)
    k_tr<<<(2048 * 256 + 255) / 256, 256>>>(W1, W1T, 2048, 256);
    k_prep_mid<<<(3 * 65536 + 255) / 256, 256>>>(W2, W3, W4, WmT, WmR);
    k_perm<<<(2048 * 256 + 255) / 256, 256>>>(W1, W1P);

    // RFF features
    k_y<<<(n * 256 + 255) / 256, 256>>>(x, B, yb, n);

    dim3 g256((n + 127) / 128, 1);
    // forward (layer 4 stores h4 UNROUNDED: feeds f directly)
    k_mma<1><<<g256, 512, SMEM>>>(yb, 2048, W1T, 2048, b1, nullptr, h1, s1, 256, 2048, n, 1,
                                  nullptr, nullptr, nullptr);
    k_mma<1><<<g256, 512, SMEM>>>(h1, 256, W2T, 256, b2, nullptr, h2, s2, 256, 256, n, 1,
                                  nullptr, nullptr, nullptr);
    k_mma<1><<<g256, 512, SMEM>>>(h2, 256, W3T, 256, b3, nullptr, h3, s3, 256, 256, n, 1,
                                  nullptr, nullptr, nullptr);
    k_mma<1><<<g256, 512, SMEM>>>(h3, 256, W4T, 256, b4, nullptr, h4, s4, 256, 256, n, 0,
                                  nullptr, nullptr, nullptr);

    // head
    k_head<<<(n + 7) / 8, 256>>>(h4, s4, W5, b5, out_f, g0, n);

    // backward
    k_mma<2><<<g256, 512, SMEM>>>(g0, 256, W4R, 256, nullptr, s3, g1b, nullptr, 256, 256, n, 1,
                                  nullptr, nullptr, nullptr);
    k_mma<2><<<g256, 512, SMEM>>>(g1b, 256, W3R, 256, nullptr, s2, g0, nullptr, 256, 256, n, 1,
                                  nullptr, nullptr, nullptr);
    k_mma<2><<<g256, 512, SMEM>>>(g0, 256, W2R, 256, nullptr, s1, g1b, nullptr, 256, 256, n, 1,
                                  nullptr, nullptr, nullptr);

    // alpha
    k_biot<<<(n + 255) / 256, 256>>>(x, bdry, out_alpha, n, M);

    // gy GEMM fused with df contraction
    dim3 gGy((n + 127) / 128, 8);
    k_mma<3><<<gGy, 512, SMEM>>>(g1b, 256, W1P, 256, nullptr, nullptr, nullptr, nullptr, 256, 256, n, 0,
                                 yb, B, dfp);

    // finish
    k_finish<<<(n + 255) / 256, 256>>>(dfp, out_alpha, out_df, out_cur, n);
}

// round 11
// speedup vs baseline: 1.8339x; 1.8321x over previous
#include <cuda_runtime.h>
#include <cuda_fp16.h>
#include <math.h>
#include <cstdint>

#define NMAX 65536
#define TWO_PI_F  6.283185307179586f
#define PI_F      3.14159265358979f
#define INV_4PI_F 0.07957747154594767f

// ---------------- scratch ----------------
__device__ __half d_W1T[2048 * 256];
__device__ __half d_W1P[2048 * 256];
__device__ __half d_WmidT[3 * 256 * 256];
__device__ __half d_WmidR[3 * 256 * 256];
__device__ __half d_y[(size_t)NMAX * 2048];     // fp16 [sin | cos]
__device__ __half d_hh[(size_t)3 * NMAX * 256]; // h1..h3 fp16
__device__ float  d_h4[(size_t)NMAX * 256];     // h4 fp32 (feeds f)
__device__ __half d_sh[(size_t)3 * NMAX * 256]; // s1..s3 fp16
__device__ float  d_s4[(size_t)NMAX * 256];     // s4 fp32
__device__ __half d_g[(size_t)2 * NMAX * 256];
__device__ float  d_dfp[(size_t)8 * NMAX * 3];

// ---------------- helpers ----------------
__device__ __forceinline__ void mma_f16(float* d, const uint32_t* a, const uint32_t* b) {
    asm volatile(
        "mma.sync.aligned.m16n8k16.row.col.f32.f16.f16.f32 "
        "{%0,%1,%2,%3}, {%4,%5,%6,%7}, {%8,%9}, {%0,%1,%2,%3};"
        : "+f"(d[0]), "+f"(d[1]), "+f"(d[2]), "+f"(d[3])
        : "r"(a[0]), "r"(a[1]), "r"(a[2]), "r"(a[3]), "r"(b[0]), "r"(b[1]));
}
__device__ __forceinline__ void cp_async16(uint32_t dst, const void* src, bool pred) {
    int sz = pred ? 16 : 0;
    asm volatile("cp.async.cg.shared.global [%0], [%1], 16, %2;"
                 :: "r"(dst), "l"(src), "r"(sz));
}
__device__ __forceinline__ void cp_commit() {
    asm volatile("cp.async.commit_group;" ::: "memory");
}
__device__ __forceinline__ float clip1(float v) { return fminf(fmaxf(v, -1.0f), 1.0f); }

__device__ __forceinline__ void sincos2pi_poly(float r, float* s, float* c) {
    float x = PI_F * r;
    float t = x * x;
    float sp = -1.0f / 5040.0f + t * (1.0f / 362880.0f);
    sp = 1.0f / 120.0f + t * sp;
    sp = -1.0f / 6.0f + t * sp;
    sp = x + x * t * sp;
    float cp = 1.0f / 40320.0f;
    cp = -1.0f / 720.0f + t * cp;
    cp = 1.0f / 24.0f + t * cp;
    cp = -0.5f + t * cp;
    cp = 1.0f + t * cp;
    float u = sp * cp;
    *s = u + u;
    *c = fmaf(-2.0f * sp, sp, 1.0f);
}

// ---------------- weight prep ----------------
__global__ void k_tr(const float* __restrict__ in, __half* __restrict__ out, int R, int C) {
    int idx = blockIdx.x * blockDim.x + threadIdx.x;
    if (idx >= R * C) return;
    int r = idx / C, c = idx - r * C;
    out[(size_t)c * R + r] = __float2half_rn(in[idx]);
}
__global__ void k_prep_mid(const float* __restrict__ W2, const float* __restrict__ W3,
                           const float* __restrict__ W4,
                           __half* __restrict__ outT, __half* __restrict__ outR) {
    int idx = blockIdx.x * blockDim.x + threadIdx.x;
    if (idx >= 3 * 65536) return;
    int m = idx >> 16, e = idx & 65535;
    const float* W = (m == 0) ? W2 : (m == 1) ? W3 : W4;
    __half v = __float2half_rn(W[e]);
    outR[idx] = v;
    int r = e >> 8, c = e & 255;
    outT[(m << 16) + c * 256 + r] = v;
}
__global__ void k_perm(const float* __restrict__ W1, __half* __restrict__ out) {
    int idx = blockIdx.x * blockDim.x + threadIdx.x;
    if (idx >= 2048 * 256) return;
    int rp = idx >> 8, q = idx & 255;
    int t = rp >> 8, s = rp & 255;
    int j = (s < 128) ? (t * 128 + s) : (1024 + t * 128 + (s - 128));
    out[idx] = __float2half_rn(W1[(size_t)j * 256 + q]);
}

// ---------------- RFF features (fp16 output) ----------------
__global__ void k_y(const float* __restrict__ x, const float* __restrict__ B,
                    __half* __restrict__ y, int n) {
    int idx = blockIdx.x * blockDim.x + threadIdx.x;
    if (idx >= n * 256) return;
    int p = idx >> 8, j0 = (idx & 255) << 2;
    float x0 = clip1(x[p * 3 + 0]);
    float x1 = clip1(x[p * 3 + 1]);
    float x2 = clip1(x[p * 3 + 2]);
    float4 B0 = *(const float4*)(B + j0);
    float4 B1 = *(const float4*)(B + 1024 + j0);
    float4 B2 = *(const float4*)(B + 2048 + j0);
    float tv[4], sv[4], cv[4];
    tv[0] = x0 * B0.x + x1 * B1.x + x2 * B2.x;
    tv[1] = x0 * B0.y + x1 * B1.y + x2 * B2.y;
    tv[2] = x0 * B0.z + x1 * B1.z + x2 * B2.z;
    tv[3] = x0 * B0.w + x1 * B1.w + x2 * B2.w;
    bool mufu = (((idx >> 5) % 3) == 0);
#pragma unroll
    for (int q = 0; q < 4; q++) {
        float r = tv[q] - rintf(tv[q]);
        if (mufu) __sincosf(TWO_PI_F * r, &sv[q], &cv[q]);
        else sincos2pi_poly(r, &sv[q], &cv[q]);
    }
    union { __half2 h2[2]; uint2 u; } ps, pc;
    ps.h2[0] = __floats2half2_rn(sv[0], sv[1]);
    ps.h2[1] = __floats2half2_rn(sv[2], sv[3]);
    pc.h2[0] = __floats2half2_rn(cv[0], cv[1]);
    pc.h2[1] = __floats2half2_rn(cv[2], cv[3]);
    *(uint2*)(y + (size_t)p * 2048 + j0) = ps.u;
    *(uint2*)(y + (size_t)p * 2048 + 1024 + j0) = pc.u;
}

// ---------------- fp16 mma.sync GEMM: 512 threads, warp tile 32x64, K_stage=64 ----------------
#define LDSWH 72                 // halfs per smem row (64 data + 8 pad)
#define ASH (128 * LDSWH)        // halfs
#define BSH (256 * LDSWH)
#define STGH (ASH + BSH)         // 27648 halfs = 55296 bytes per stage

__device__ __forceinline__ void issue_stage(uint32_t sAb, uint32_t sBb,
        const __half* __restrict__ A, int lda,
        const __half* __restrict__ Bm, int ldb,
        int p0, int c0, int koff, int tid, int n) {
    const __half* Ab = A + (size_t)p0 * lda + koff;
#pragma unroll
    for (int it = 0; it < 2; it++) {
        int lin = tid + 512 * it;
        int row = lin >> 3, q = (lin & 7) << 3;   // 8 halfs (16B) per chunk
        cp_async16(sAb + (uint32_t)(row * LDSWH + q) * 2, Ab + (size_t)row * lda + q, p0 + row < n);
    }
    const __half* Bb = Bm + (size_t)c0 * ldb + koff;
#pragma unroll
    for (int it = 0; it < 4; it++) {
        int lin = tid + 512 * it;
        int row = lin >> 3, q = (lin & 7) << 3;
        cp_async16(sBb + (uint32_t)(row * LDSWH + q) * 2, Bb + (size_t)row * ldb + q, true);
    }
}

// EPI 1: softplus->C(fp16), sigmoid->Cs(fp16)
// EPI 4: layer-4: softplus->C(fp32), sigmoid->Cs(fp32)
// EPI 2: (v*Sm)->C(fp16), Sm fp16
// EPI 3: fused df contraction -> dfpart
template <int EPI>
__global__ __launch_bounds__(512, 1)
void k_mma(const __half* __restrict__ A, int lda,
           const __half* __restrict__ Bm, int ldb,
           const float* __restrict__ bias, const __half* __restrict__ Sm,
           void* Cv, void* Csv,
           int ldc, int K, int n,
           const __half* __restrict__ Ybuf, const float* __restrict__ Brff,
           float* __restrict__ dfpart) {
    extern __shared__ __half smem_h[];
    const int tid = threadIdx.x;
    const int p0 = blockIdx.x * 128;
    const int c0 = blockIdx.y * 256;
    const int wid = tid >> 5, lane = tid & 31;
    const int wm = (wid & 3) * 32;
    const int wn = (wid >> 2) * 64;
    const int tr = lane >> 2, tc = lane & 3;

    uint32_t smem_u32 = (uint32_t)__cvta_generic_to_shared(smem_h);

    float acc[2][8][4];
#pragma unroll
    for (int mi = 0; mi < 2; mi++)
#pragma unroll
        for (int ni = 0; ni < 8; ni++)
#pragma unroll
            for (int q = 0; q < 4; q++) acc[mi][ni][q] = 0.0f;

    const int nst = K >> 6;   // K_stage = 64
    issue_stage(smem_u32, smem_u32 + ASH * 2, A, lda, Bm, ldb, p0, c0, 0, tid, n);
    cp_commit();
    issue_stage(smem_u32 + STGH * 2, smem_u32 + (STGH + ASH) * 2, A, lda, Bm, ldb, p0, c0, 64, tid, n);
    cp_commit();

    for (int i = 0; i < nst; i++) {
        if (i + 1 < nst) asm volatile("cp.async.wait_group 1;" ::: "memory");
        else             asm volatile("cp.async.wait_group 0;" ::: "memory");
        __syncthreads();
        if (i + 2 < nst) {
            int sl = (i + 2) % 3;
            issue_stage(smem_u32 + (uint32_t)(sl * STGH) * 2,
                        smem_u32 + (uint32_t)(sl * STGH + ASH) * 2,
                        A, lda, Bm, ldb, p0, c0, (i + 2) * 64, tid, n);
            cp_commit();
        }
        const __half* cA = smem_h + (i % 3) * STGH;
        const __half* cB = cA + ASH;
#pragma unroll
        for (int k16 = 0; k16 < 4; k16++) {
            const int kc = k16 * 16 + 2 * tc;
            uint32_t af[2][4], bf[8][2];
#pragma unroll
            for (int mi = 0; mi < 2; mi++) {
                const __half* base = cA + (wm + mi * 16 + tr) * LDSWH + kc;
                af[mi][0] = *(const uint32_t*)(base);
                af[mi][1] = *(const uint32_t*)(base + 8 * LDSWH);
                af[mi][2] = *(const uint32_t*)(base + 8);
                af[mi][3] = *(const uint32_t*)(base + 8 * LDSWH + 8);
            }
#pragma unroll
            for (int ni = 0; ni < 8; ni++) {
                const __half* baseb = cB + (wn + ni * 8 + tr) * LDSWH + kc;
                bf[ni][0] = *(const uint32_t*)(baseb);
                bf[ni][1] = *(const uint32_t*)(baseb + 8);
            }
#pragma unroll
            for (int mi = 0; mi < 2; mi++)
#pragma unroll
                for (int ni = 0; ni < 8; ni++)
                    mma_f16(acc[mi][ni], af[mi], bf[ni]);
        }
        __syncthreads();
    }

    if (EPI == 3) {
        const int jt = c0 >> 1;
        const bool coshalf = (wn >= 128);
        float sum3[2][2][3];
#pragma unroll
        for (int mi = 0; mi < 2; mi++)
#pragma unroll
            for (int hf = 0; hf < 2; hf++)
#pragma unroll
                for (int d = 0; d < 3; d++) sum3[mi][hf][d] = 0.f;

#pragma unroll
        for (int ni = 0; ni < 8; ni++) {
            int cl = wn + ni * 8 + 2 * tc;
            int j = jt + (coshalf ? cl - 128 : cl);
            float2 B0 = *(const float2*)(Brff + j);
            float2 B1 = *(const float2*)(Brff + 1024 + j);
            float2 B2 = *(const float2*)(Brff + 2048 + j);
            int yoff = coshalf ? j : (1024 + j);
#pragma unroll
            for (int mi = 0; mi < 2; mi++) {
#pragma unroll
                for (int hf = 0; hf < 2; hf++) {
                    int p = p0 + wm + mi * 16 + tr + 8 * hf;
                    float2 t2 = __half22float2(*(const __half2*)(Ybuf + (size_t)p * 2048 + yoff));
                    float f0 = coshalf ? -t2.x : t2.x;
                    float f1 = coshalf ? -t2.y : t2.y;
                    float e0 = acc[mi][ni][2 * hf] * f0;
                    float e1 = acc[mi][ni][2 * hf + 1] * f1;
                    sum3[mi][hf][0] += e0 * B0.x + e1 * B0.y;
                    sum3[mi][hf][1] += e0 * B1.x + e1 * B1.y;
                    sum3[mi][hf][2] += e0 * B2.x + e1 * B2.y;
                }
            }
        }
        float* red = (float*)smem_h;
        __syncthreads();
#pragma unroll
        for (int mi = 0; mi < 2; mi++)
#pragma unroll
            for (int hf = 0; hf < 2; hf++)
#pragma unroll
                for (int d = 0; d < 3; d++) {
                    float v = sum3[mi][hf][d];
                    v += __shfl_xor_sync(0xffffffffu, v, 1);
                    v += __shfl_xor_sync(0xffffffffu, v, 2);
                    if (tc == 0) {
                        int p_local = wm + mi * 16 + tr + 8 * hf;
                        red[p_local * 16 + d * 4 + (wn >> 6)] = v;
                    }
                }
        __syncthreads();
        if (tid < 128) {
            int p = p0 + tid;
#pragma unroll
            for (int d = 0; d < 3; d++) {
                float s = red[tid * 16 + d * 4 + 0] + red[tid * 16 + d * 4 + 1] +
                          red[tid * 16 + d * 4 + 2] + red[tid * 16 + d * 4 + 3];
                dfpart[((size_t)blockIdx.y * NMAX + p) * 3 + d] = TWO_PI_F * s;
            }
        }
        return;
    }

#pragma unroll
    for (int mi = 0; mi < 2; mi++) {
        const int r0 = p0 + wm + mi * 16 + tr;
#pragma unroll
        for (int ni = 0; ni < 8; ni++) {
            const int gc = c0 + wn + ni * 8 + 2 * tc;
            float2 bia = make_float2(0.f, 0.f);
            if (EPI == 1 || EPI == 4) bia = *(const float2*)(bias + gc);
#pragma unroll
            for (int hf = 0; hf < 2; hf++) {
                const int p = r0 + 8 * hf;
                if (p >= n) continue;
                float v0 = acc[mi][ni][2 * hf];
                float v1 = acc[mi][ni][2 * hf + 1];
                const size_t off = (size_t)p * ldc + gc;
                if (EPI == 1 || EPI == 4) {
                    float z0 = v0 + bia.x, z1 = v1 + bia.y;
                    float e0 = __expf(-fabsf(z0)), e1 = __expf(-fabsf(z1));
                    float h0 = fmaxf(z0, 0.f) + log1pf(e0);
                    float h1 = fmaxf(z1, 0.f) + log1pf(e1);
                    float s0 = (z0 >= 0.f) ? 1.f / (1.f + e0) : e0 / (1.f + e0);
                    float s1 = (z1 >= 0.f) ? 1.f / (1.f + e1) : e1 / (1.f + e1);
                    if (EPI == 1) {
                        *(__half2*)((__half*)Cv + off) = __floats2half2_rn(h0, h1);
                        *(__half2*)((__half*)Csv + off) = __floats2half2_rn(s0, s1);
                    } else {
                        *(float2*)((float*)Cv + off) = make_float2(h0, h1);
                        *(float2*)((float*)Csv + off) = make_float2(s0, s1);
                    }
                } else {   // EPI == 2
                    float2 sm2 = __half22float2(*(const __half2*)(Sm + off));
                    *(__half2*)((__half*)Cv + off) = __floats2half2_rn(v0 * sm2.x, v1 * sm2.y);
                }
            }
        }
    }
}

// ---------------- head: f = h4 . W5 + b5, g4 = fp16(W5 * s4) ----------------
__global__ void k_head(const float* __restrict__ h4, const float* __restrict__ s4,
                       const float* __restrict__ W5, const float* __restrict__ b5,
                       float* __restrict__ out_f, __half* __restrict__ g4, int n) {
    __shared__ float sw[256];
    int tid = threadIdx.x;
    sw[tid] = W5[tid];
    __syncthreads();
    int p = blockIdx.x * 8 + (tid >> 5);
    int lane = tid & 31;
    if (p >= n) return;
    float acc = 0.f;
    const float* hr = h4 + (size_t)p * 256;
    const float* sr = s4 + (size_t)p * 256;
    __half* gr = g4 + (size_t)p * 256;
#pragma unroll
    for (int i = lane; i < 256; i += 32) {
        float wv = sw[i];
        acc += hr[i] * wv;
        gr[i] = __float2half_rn(wv * sr[i]);
    }
#pragma unroll
    for (int o = 16; o; o >>= 1) acc += __shfl_xor_sync(0xffffffffu, acc, o);
    if (lane == 0) out_f[p] = acc + b5[0];
}

// ---------------- Biot-Savart ----------------
__global__ void k_biot(const float* __restrict__ x, const float* __restrict__ bdry,
                       float* __restrict__ out_alpha, int n, int M) {
    __shared__ float bx[512], by[512], bz[512];
    __shared__ float sgx[512], sgy[512], sgz[512];
    __shared__ float smx[512], smy[512], smz[512];
    int tid = threadIdx.x;
    for (int m = tid; m < M; m += blockDim.x) {
        bx[m] = bdry[m * 3 + 0];
        by[m] = bdry[m * 3 + 1];
        bz[m] = bdry[m * 3 + 2];
    }
    __syncthreads();
    for (int m = tid; m < M; m += blockDim.x) {
        int m2 = (m + 1) == M ? 0 : m + 1;
        sgx[m] = bx[m2] - bx[m];
        sgy[m] = by[m2] - by[m];
        sgz[m] = bz[m2] - bz[m];
        smx[m] = 0.5f * (bx[m2] + bx[m]);
        smy[m] = 0.5f * (by[m2] + by[m]);
        smz[m] = 0.5f * (bz[m2] + bz[m]);
    }
    __syncthreads();
    int p = blockIdx.x * blockDim.x + tid;
    if (p >= n) return;
    float x0 = clip1(x[p * 3 + 0]);
    float x1 = clip1(x[p * 3 + 1]);
    float x2 = clip1(x[p * 3 + 2]);
    float ax = 0.f, ay = 0.f, az = 0.f;
    for (int m = 0; m < M; m++) {
        float dx = x0 - smx[m], dy = x1 - smy[m], dz = x2 - smz[m];
        float cxv = sgy[m] * dz - sgz[m] * dy;
        float cyv = sgz[m] * dx - sgx[m] * dz;
        float czv = sgx[m] * dy - sgy[m] * dx;
        float r2 = dx * dx + dy * dy + dz * dz;
        float inv = rsqrtf(r2);
        float w = inv * inv * inv;
        ax += cxv * w; ay += cyv * w; az += czv * w;
    }
    out_alpha[p * 3 + 0] = INV_4PI_F * ax;
    out_alpha[p * 3 + 1] = INV_4PI_F * ay;
    out_alpha[p * 3 + 2] = INV_4PI_F * az;
}

// ---------------- finish ----------------
__global__ void k_finish(const float* __restrict__ part, const float* __restrict__ alpha,
                         float* __restrict__ out_df, float* __restrict__ out_cur, int n) {
    int p = blockIdx.x * blockDim.x + threadIdx.x;
    if (p >= n) return;
#pragma unroll
    for (int d = 0; d < 3; d++) {
        float s = 0.f;
#pragma unroll
        for (int t = 0; t < 8; t++) s += part[((size_t)t * NMAX + p) * 3 + d];
        out_df[p * 3 + d] = s;
        out_cur[p * 3 + d] = s + alpha[p * 3 + d];
    }
}

// ---------------- launcher ----------------
extern "C" void kernel_launch(void* const* d_in, const int* in_sizes, int n_in,
                              void* d_out, int out_size) {
    const float* x    = (const float*)d_in[0];
    const float* bdry = (const float*)d_in[1];
    const float* B    = (const float*)d_in[2];
    const float* W1   = (const float*)d_in[3];
    const float* b1   = (const float*)d_in[4];
    const float* W2   = (const float*)d_in[5];
    const float* b2   = (const float*)d_in[6];
    const float* W3   = (const float*)d_in[7];
    const float* b3   = (const float*)d_in[8];
    const float* W4   = (const float*)d_in[9];
    const float* b4   = (const float*)d_in[10];
    const float* W5   = (const float*)d_in[11];
    const float* b5   = (const float*)d_in[12];

    int n = in_sizes[0] / 3;
    int M = in_sizes[1] / 3;

    float* out = (float*)d_out;
    float* out_f     = out;
    float* out_cur   = out + (size_t)n;
    float* out_df    = out + (size_t)4 * n;
    float* out_alpha = out + (size_t)7 * n;

    void* pv;
    cudaGetSymbolAddress(&pv, d_W1T);   __half* W1T = (__half*)pv;
    cudaGetSymbolAddress(&pv, d_W1P);   __half* W1P = (__half*)pv;
    cudaGetSymbolAddress(&pv, d_WmidT); __half* WmT = (__half*)pv;
    cudaGetSymbolAddress(&pv, d_WmidR); __half* WmR = (__half*)pv;
    cudaGetSymbolAddress(&pv, d_y);     __half* yb  = (__half*)pv;
    cudaGetSymbolAddress(&pv, d_hh);    __half* hh  = (__half*)pv;
    cudaGetSymbolAddress(&pv, d_h4);    float*  h4  = (float*)pv;
    cudaGetSymbolAddress(&pv, d_sh);    __half* sh  = (__half*)pv;
    cudaGetSymbolAddress(&pv, d_s4);    float*  s4  = (float*)pv;
    cudaGetSymbolAddress(&pv, d_g);     __half* gb  = (__half*)pv;
    cudaGetSymbolAddress(&pv, d_dfp);   float*  dfp = (float*)pv;

    __half *W2T = WmT, *W3T = WmT + 65536, *W4T = WmT + 2 * 65536;
    __half *W2R = WmR, *W3R = WmR + 65536, *W4R = WmR + 2 * 65536;

    const size_t HS = (size_t)NMAX * 256;
    __half *h1 = hh, *h2 = hh + HS, *h3 = hh + 2 * HS;
    __half *s1 = sh, *s2 = sh + HS, *s3 = sh + 2 * HS;
    __half *g0 = gb, *g1b = gb + HS;

    const int SMEM = 3 * STGH * 2;  // 165888 bytes
    cudaFuncSetAttribute((const void*)k_mma<1>, cudaFuncAttributeMaxDynamicSharedMemorySize, SMEM);
    cudaFuncSetAttribute((const void*)k_mma<2>, cudaFuncAttributeMaxDynamicSharedMemorySize, SMEM);
    cudaFuncSetAttribute((const void*)k_mma<3>, cudaFuncAttributeMaxDynamicSharedMemorySize, SMEM);
    cudaFuncSetAttribute((const void*)k_mma<4>, cudaFuncAttributeMaxDynamicSharedMemorySize, SMEM);

    // weight prep (fp16 outputs)
    k_tr<<<(2048 * 256 + 255) / 256, 256>>>(W1, W1T, 2048, 256);
    k_prep_mid<<<(3 * 65536 + 255) / 256, 256>>>(W2, W3, W4, WmT, WmR);
    k_perm<<<(2048 * 256 + 255) / 256, 256>>>(W1, W1P);

    // RFF features (fp16)
    k_y<<<(n * 256 + 255) / 256, 256>>>(x, B, yb, n);

    dim3 g256((n + 127) / 128, 1);
    // forward (layers 1-3 fp16 out; layer 4 fp32 out — feeds f)
    k_mma<1><<<g256, 512, SMEM>>>(yb, 2048, W1T, 2048, b1, nullptr, h1, s1, 256, 2048, n,
                                  nullptr, nullptr, nullptr);
    k_mma<1><<<g256, 512, SMEM>>>(h1, 256, W2T, 256, b2, nullptr, h2, s2, 256, 256, n,
                                  nullptr, nullptr, nullptr);
    k_mma<1><<<g256, 512, SMEM>>>(h2, 256, W3T, 256, b3, nullptr, h3, s3, 256, 256, n,
                                  nullptr, nullptr, nullptr);
    k_mma<4><<<g256, 512, SMEM>>>(h3, 256, W4T, 256, b4, nullptr, h4, s4, 256, 256, n,
                                  nullptr, nullptr, nullptr);

    // head
    k_head<<<(n + 7) / 8, 256>>>(h4, s4, W5, b5, out_f, g0, n);

    // backward
    k_mma<2><<<g256, 512, SMEM>>>(g0, 256, W4R, 256, nullptr, s3, g1b, nullptr, 256, 256, n,
                                  nullptr, nullptr, nullptr);
    k_mma<2><<<g256, 512, SMEM>>>(g1b, 256, W3R, 256, nullptr, s2, g0, nullptr, 256, 256, n,
                                  nullptr, nullptr, nullptr);
    k_mma<2><<<g256, 512, SMEM>>>(g0, 256, W2R, 256, nullptr, s1, g1b, nullptr, 256, 256, n,
                                  nullptr, nullptr, nullptr);

    // alpha
    k_biot<<<(n + 255) / 256, 256>>>(x, bdry, out_alpha, n, M);

    // gy GEMM fused with df contraction
    dim3 gGy((n + 127) / 128, 8);
    k_mma<3><<<gGy, 512, SMEM>>>(g1b, 256, W1P, 256, nullptr, nullptr, nullptr, nullptr, 256, 256, n,
                                 yb, B, dfp);

    // finish
    k_finish<<<(n + 255) / 256, 256>>>(dfp, out_alpha, out_df, out_cur, n);
}